// round 11
// baseline (speedup 1.0000x reference)
#include <cuda_runtime.h>

#define WARPS_PER_CTA 13
#define NTHREADS (WARPS_PER_CTA * 32)

#define W1P_U 8800            // ull [275][32] packed (w,w), lane-major
#define W2P_U 5120            // ull [160][32] packed
#define LINT_F 4992           // float [12][13][32]
#define CONST_F (6*32 + 16)

#define SCRATCH_U 904         // ull slots per warp (7232 B)
#define SMEM_BYTES ((W1P_U + W2P_U) * 8 + (LINT_F + CONST_F) * 4 + WARPS_PER_CTA * SCRATCH_U * 8)

typedef unsigned long long ull;

__device__ __forceinline__ ull pk2(float x, float y) {
    ull r; asm("mov.b64 %0, {%1,%2};" : "=l"(r) : "f"(x), "f"(y)); return r;
}
__device__ __forceinline__ void up2(ull v, float& x, float& y) {
    asm("mov.b64 {%0,%1}, %2;" : "=f"(x), "=f"(y) : "l"(v));
}
__device__ __forceinline__ ull swp(ull v) {
    float a, b; up2(v, a, b); return pk2(b, a);
}
__device__ __forceinline__ ull ffma2(ull a, ull b, ull c) {
    ull d; asm("fma.rn.f32x2 %0, %1, %2, %3;" : "=l"(d) : "l"(a), "l"(b), "l"(c)); return d;
}
__device__ __forceinline__ ull fadd2(ull a, ull b) {
    ull d; asm("add.rn.f32x2 %0, %1, %2;" : "=l"(d) : "l"(a), "l"(b)); return d;
}
__device__ __forceinline__ float lrelu(float v) { return v > 0.f ? v : 0.2f * v; }

// lane-softmax for ONE packed column: (ax, ay) raw leaky'd scores ->
// packed normalized attention weight for this lane.
__device__ __forceinline__ ull softmax_col(float ax, float ay) {
    float mx = ax, my = ay;
#pragma unroll
    for (int off = 16; off > 0; off >>= 1) {
        mx = fmaxf(mx, __shfl_xor_sync(0xffffffffu, mx, off));
        my = fmaxf(my, __shfl_xor_sync(0xffffffffu, my, off));
    }
    float ex = __expf(ax - mx), ey = __expf(ay - my);
    float sx = ex, sy = ey;
#pragma unroll
    for (int off = 16; off > 0; off >>= 1) {
        sx += __shfl_xor_sync(0xffffffffu, sx, off);
        sy += __shfl_xor_sync(0xffffffffu, sy, off);
    }
    return pk2(__fdividef(ex, sx), __fdividef(ey, sy));
}

__global__ void __launch_bounds__(NTHREADS, 1) gcn_kernel(
    const float* __restrict__ x,
    const float* __restrict__ c1w, const float* __restrict__ c1b,
    const float* __restrict__ g1,  const float* __restrict__ be1,
    const float* __restrict__ m1,  const float* __restrict__ v1,
    const float* __restrict__ c2w, const float* __restrict__ c2b,
    const float* __restrict__ g2,  const float* __restrict__ be2,
    const float* __restrict__ m2,  const float* __restrict__ v2,
    const float* __restrict__ lw,  const float* __restrict__ lb,
    float* __restrict__ out, int B)
{
    extern __shared__ ull smu[];
    ull*   w1P  = smu;                 // [k][32] packed (w,w)
    ull*   w2P  = w1P + W1P_U;
    float* linT = (float*)(w2P + W2P_U);   // [q][j][32]
    float* sb1  = linT + LINT_F;
    float* sb2  = sb1 + 32;
    float* ss1  = sb2 + 32;
    float* sbb1 = ss1 + 32;
    float* ss2  = sbb1 + 32;
    float* sbb2 = ss2 + 32;
    float* slb  = sbb2 + 32;           // 16 floats (13 used)
    ull*   scratch = (ull*)(slb + 16);

    const int tid = threadIdx.x;

    // ---- cooperative weight staging (transposed, pre-packed (w,w)) ----
    for (int i = tid; i < W1P_U; i += NTHREADS) {
        int k = i >> 5, o = i & 31;
        float w = c1w[o * 275 + k];
        w1P[i] = pk2(w, w);
    }
    for (int i = tid; i < W2P_U; i += NTHREADS) {
        int k = i >> 5, o = i & 31;
        float w = c2w[o * 160 + k];
        w2P[i] = pk2(w, w);
    }
    for (int i = tid; i < LINT_F; i += NTHREADS) {
        int n = i & 31, tj = i >> 5;
        int j = tj % 13, q = tj / 13;
        linT[i] = lw[j * 384 + n * 12 + q];
    }
    if (tid < 32) {
        sb1[tid] = c1b[tid];
        sb2[tid] = c2b[tid];
        float inv1 = g1[tid] / sqrtf(v1[tid] + 1e-5f);
        ss1[tid] = inv1; sbb1[tid] = be1[tid] - m1[tid] * inv1;
        float inv2 = g2[tid] / sqrtf(v2[tid] + 1e-5f);
        ss2[tid] = inv2; sbb2[tid] = be2[tid] - m2[tid] * inv2;
    }
    if (tid < 13) slb[tid] = lb[tid];
    __syncthreads();

    const int warp = tid >> 5, lane = tid & 31;
    const int b = blockIdx.x * WARPS_PER_CTA + warp;
    if (b >= B) return;

    ull* scw = scratch + warp * SCRATCH_U;
    // phase-overlapped layouts (ull offsets within scw):
    ull* xpad2 = scw;            // [25][36]  (900)   conv1 input, packed (xa,na)
    ull* hsh2  = scw;            // [32][26]  (832)   layer-1 h rows (aliases xpad2)
    ull* ppad2 = scw;            // [32][16]  (512)   layer-2 padded input
    ull* cshN  = scw + 512;      // [32][12]  (384)   conv2 out rows (xa,na)

    // ---- stage input, circularly padded, packed (xa, na) ----
    const float* xb = x + (size_t)b * 1250;
    for (int i = lane; i < 900; i += 32) {
        int p = i % 36, ck = i / 36;     // ck = c*5 + h
        float vx = 0.f, vy = 0.f;
        if (p < 35) {
            int wsrc = (p + 20) % 25;    // padded p -> orig (p-5) mod 25
            vx = xb[ck * 50 + wsrc];
            vy = xb[ck * 50 + 25 + wsrc];
        }
        xpad2[i] = pk2(vx, vy);
    }
    __syncwarp();

    // ======== LAYER 1: conv1 (packed, 2-block w-split to cap regs ~140) ========
    ull acc[25];
    {
        float bv = sb1[lane];
        ull bia = pk2(bv, bv);
#pragma unroll
        for (int w = 0; w < 25; w++) acc[w] = bia;
    }
#pragma unroll 1
    for (int ck = 0; ck < 25; ck++) {
        const ull* row = xpad2 + ck * 36;
        ull wr[11];
        const ull* wp = w1P + ck * 11 * 32 + lane;
#pragma unroll
        for (int kw = 0; kw < 11; kw++) wr[kw] = wp[kw * 32];

        // block 0: outputs w=0..12, window xr[0..22] (load xr[0..23])
        {
            ull xw[24];
            const ulonglong2* r2 = (const ulonglong2*)row;
#pragma unroll
            for (int q = 0; q < 12; q++) { ulonglong2 t = r2[q]; xw[2*q] = t.x; xw[2*q+1] = t.y; }
#pragma unroll
            for (int kw = 0; kw < 11; kw++)
#pragma unroll
                for (int w = 0; w < 13; w++)
                    acc[w] = ffma2(wr[kw], xw[w + kw], acc[w]);
        }
        // block 1: outputs w=13..24, window xr[13..34] (load xr[12..35])
        {
            ull xw[24];
            const ulonglong2* r2 = (const ulonglong2*)row + 6;
#pragma unroll
            for (int q = 0; q < 12; q++) { ulonglong2 t = r2[q]; xw[2*q] = t.x; xw[2*q+1] = t.y; }
#pragma unroll
            for (int kw = 0; kw < 11; kw++)
#pragma unroll
                for (int w = 13; w < 25; w++)
                    acc[w] = ffma2(wr[kw], xw[w + kw - 12], acc[w]);
        }
    }

    // h rows (with bias) to warp-local shared, packed
#pragma unroll
    for (int f = 0; f < 25; f++) hsh2[lane * 26 + f] = acc[f];
    __syncwarp();

    // ---- attention 1, STREAMED per column m: dot -> softmax -> AV ----
    ull o1[25];
#pragma unroll
    for (int f = 0; f < 25; f++) o1[f] = 0;
#pragma unroll 4
    for (int m = 0; m < 32; m++) {
        const ull* hm = hsh2 + m * 26;
        const ulonglong2* hm2 = (const ulonglong2*)hm;
        ull p0 = 0, p1 = 0;
#pragma unroll
        for (int q = 0; q < 12; q++) {
            ulonglong2 t = hm2[q];
            p0 = ffma2(acc[2*q],   t.x, p0);
            p1 = ffma2(acc[2*q+1], t.y, p1);
        }
        p0 = fadd2(p0, p1);
        p0 = ffma2(acc[24], hm[24], p0);
        float sx, sy; up2(p0, sx, sy);
        ull a = softmax_col(lrelu(sx), lrelu(sy));
#pragma unroll
        for (int q = 0; q < 12; q++) {
            ulonglong2 t = hm2[q];
            o1[2*q]   = ffma2(a, t.x, o1[2*q]);
            o1[2*q+1] = ffma2(a, t.y, o1[2*q+1]);
        }
        o1[24] = ffma2(a, hm[24], o1[24]);
    }

    // ---- BN1 -> pairwise maxpool (drop f=24) -> relu ----
    ull p2[12];
    {
        float s1 = ss1[lane], b1v = sbb1[lane];
        ull sc = pk2(s1, s1), bo = pk2(b1v, b1v);
#pragma unroll
        for (int j = 0; j < 12; j++) {
            ull y0 = ffma2(o1[2*j],   sc, bo);
            ull y1 = ffma2(o1[2*j+1], sc, bo);
            float a0, c0, a1, c1;
            up2(y0, a0, c0); up2(y1, a1, c1);
            p2[j] = pk2(fmaxf(fmaxf(a0, a1), 0.f), fmaxf(fmaxf(c0, c1), 0.f));
        }
    }
    __syncwarp();   // scratch reuse boundary (hsh2 dead)

    // ======== LAYER 2 ========
    {
        ull* pr = ppad2 + lane * 16;     // circular pad 2 on width 12
#pragma unroll
        for (int j = 0; j < 12; j++) pr[2 + j] = p2[j];
        pr[0]  = p2[10]; pr[1]  = p2[11];
        pr[14] = p2[0];  pr[15] = p2[1];
    }
    __syncwarp();

    // conv2: 32 in-channels, 5 taps, width 12, packed branches
    ull a2[12];
    {
        float bv = sb2[lane];
        ull bia = pk2(bv, bv);
#pragma unroll
        for (int w = 0; w < 12; w++) a2[w] = bia;
    }
#pragma unroll 1
    for (int i = 0; i < 32; i++) {
        const ulonglong2* pr2 = (const ulonglong2*)(ppad2 + i * 16);
        ull prr[16];
#pragma unroll
        for (int q = 0; q < 8; q++) {
            ulonglong2 t = pr2[q];
            prr[2*q] = t.x; prr[2*q+1] = t.y;
        }
        ull wr[5];
        const ull* wp = w2P + i * 5 * 32 + lane;
#pragma unroll
        for (int kw = 0; kw < 5; kw++) wr[kw] = wp[kw * 32];
#pragma unroll
        for (int kw = 0; kw < 5; kw++)
#pragma unroll
            for (int w = 0; w < 12; w++)
                a2[w] = ffma2(wr[kw], prr[w + kw], a2[w]);
    }

    // store conv2 rows (xa,na); own swapped copy kept in regs
    ull c2s[12];
    {
        ull* cN = cshN + lane * 12;
#pragma unroll
        for (int w = 0; w < 12; w++) {
            cN[w] = a2[w];
            c2s[w] = swp(a2[w]);
        }
    }
    __syncwarp();

    // ---- attention 2 (cross branches), STREAMED: att = (att_n2, att_x2) ----
    ull o2[12];
#pragma unroll
    for (int f = 0; f < 12; f++) o2[f] = 0;
#pragma unroll 4
    for (int m = 0; m < 32; m++) {
        const ulonglong2* hm2 = (const ulonglong2*)(cshN + m * 12);
        ull hv[12];
        ull p0 = 0, p1 = 0;
#pragma unroll
        for (int q = 0; q < 6; q++) {
            ulonglong2 t = hm2[q];
            hv[2*q] = t.x; hv[2*q+1] = t.y;
            p0 = ffma2(c2s[2*q],   t.x, p0);
            p1 = ffma2(c2s[2*q+1], t.y, p1);
        }
        p0 = fadd2(p0, p1);
        float sx, sy; up2(p0, sx, sy);
        ull a = softmax_col(lrelu(sx), lrelu(sy));
        // AV against swapped rows: o2 = (n2_val, x2_val)
#pragma unroll
        for (int f = 0; f < 12; f++)
            o2[f] = ffma2(a, swp(hv[f]), o2[f]);
    }

    // BN2 -> maxpool -> relu; unpack into x2p / n2p
    float opx[6], opn[6];
    {
        float s2 = ss2[lane], b2v = sbb2[lane];
        ull sc = pk2(s2, s2), bo = pk2(b2v, b2v);
#pragma unroll
        for (int j = 0; j < 6; j++) {
            ull y0 = ffma2(o2[2*j],   sc, bo);
            ull y1 = ffma2(o2[2*j+1], sc, bo);
            float n0, x0, n1, x1;
            up2(y0, n0, x0); up2(y1, n1, x1);
            opx[j] = fmaxf(fmaxf(x0, x1), 0.f);
            opn[j] = fmaxf(fmaxf(n0, n1), 0.f);
        }
    }

    // ======== final linear: flat[n*12+q], q<6 -> x2p, q>=6 -> n2p ========
    float part[13];
#pragma unroll
    for (int j = 0; j < 13; j++) part[j] = 0.f;
#pragma unroll
    for (int q = 0; q < 12; q++) {
        float v = (q < 6) ? opx[q] : opn[q - 6];
        const float* wrow = linT + q * 13 * 32 + lane;
#pragma unroll
        for (int j = 0; j < 13; j++) part[j] = fmaf(v, wrow[j * 32], part[j]);
    }
#pragma unroll
    for (int off = 16; off > 0; off >>= 1)
#pragma unroll
        for (int j = 0; j < 13; j++)
            part[j] += __shfl_xor_sync(0xffffffffu, part[j], off);

    if (lane == 0) {
#pragma unroll
        for (int j = 0; j < 13; j++)
            out[(size_t)b * 13 + j] = part[j] + slb[j];
    }
}

extern "C" void kernel_launch(void* const* d_in, const int* in_sizes, int n_in,
                              void* d_out, int out_size) {
    const float* x   = (const float*)d_in[0];
    const float* c1w = (const float*)d_in[1];
    const float* c1b = (const float*)d_in[2];
    const float* g1  = (const float*)d_in[3];
    const float* be1 = (const float*)d_in[4];
    const float* m1  = (const float*)d_in[5];
    const float* v1  = (const float*)d_in[6];
    const float* c2w = (const float*)d_in[7];
    const float* c2b = (const float*)d_in[8];
    const float* g2  = (const float*)d_in[9];
    const float* be2 = (const float*)d_in[10];
    const float* m2  = (const float*)d_in[11];
    const float* v2  = (const float*)d_in[12];
    const float* lw  = (const float*)d_in[13];
    const float* lb  = (const float*)d_in[14];
    float* out = (float*)d_out;

    int B = in_sizes[0] / 1250;   // 16384
    int grid = (B + WARPS_PER_CTA - 1) / WARPS_PER_CTA;

    cudaFuncSetAttribute(gcn_kernel, cudaFuncAttributeMaxDynamicSharedMemorySize, SMEM_BYTES);
    gcn_kernel<<<grid, NTHREADS, SMEM_BYTES>>>(x, c1w, c1b, g1, be1, m1, v1,
                                               c2w, c2b, g2, be2, m2, v2,
                                               lw, lb, out, B);
}

// round 12
// speedup vs baseline: 1.6264x; 1.6264x over previous
#include <cuda_runtime.h>

#define WARPS_PER_CTA 12
#define NTHREADS (WARPS_PER_CTA * 32)

#define W1P_U 8800            // ull [275][32] packed (w,w), lane-major
#define W2P_U 5120            // ull [160][32] packed
#define LINT_F 4992           // float [12][13][32]
#define CONST_F (6*32 + 16)

#define SCRATCH_U 904         // ull slots per warp (7232 B)
#define SMEM_BYTES ((W1P_U + W2P_U) * 8 + (LINT_F + CONST_F) * 4 + WARPS_PER_CTA * SCRATCH_U * 8)

typedef unsigned long long ull;

__device__ __forceinline__ ull pk2(float x, float y) {
    ull r; asm("mov.b64 %0, {%1,%2};" : "=l"(r) : "f"(x), "f"(y)); return r;
}
__device__ __forceinline__ void up2(ull v, float& x, float& y) {
    asm("mov.b64 {%0,%1}, %2;" : "=f"(x), "=f"(y) : "l"(v));
}
__device__ __forceinline__ ull swp(ull v) {
    float a, b; up2(v, a, b); return pk2(b, a);
}
__device__ __forceinline__ ull ffma2(ull a, ull b, ull c) {
    ull d; asm("fma.rn.f32x2 %0, %1, %2, %3;" : "=l"(d) : "l"(a), "l"(b), "l"(c)); return d;
}
__device__ __forceinline__ ull fadd2(ull a, ull b) {
    ull d; asm("add.rn.f32x2 %0, %1, %2;" : "=l"(d) : "l"(a), "l"(b)); return d;
}
// branch-free leaky relu on the fma/alu pipes (no predicate)
__device__ __forceinline__ float lrelu(float v) { return fmaxf(v, 0.2f * v); }

// warp-max of a float via order-preserving integer map + redux.sync.max.u32
// (fp32 redux doesn't exist on sm_103; integer redux does)
__device__ __forceinline__ unsigned redux_max_u32(unsigned v) {
    unsigned r; asm("redux.sync.max.u32 %0, %1, 0xffffffff;" : "=r"(r) : "r"(v)); return r;
}
__device__ __forceinline__ float warp_max_f(float f) {
    unsigned b = __float_as_uint(f);
    unsigned u = b ^ ((unsigned)((int)b >> 31) | 0x80000000u);     // monotone encode
    unsigned m = redux_max_u32(u);
    unsigned mb = m ^ ((unsigned)((int)(~m) >> 31) | 0x80000000u); // decode
    return __uint_as_float(mb);
}

// lane-softmax for ONE packed column: (ax, ay) raw leaky'd scores ->
// packed normalized attention weight for this lane.
__device__ __forceinline__ ull softmax_col(float ax, float ay) {
    float mx = warp_max_f(ax), my = warp_max_f(ay);
    float ex = __expf(ax - mx), ey = __expf(ay - my);
    float sx = ex, sy = ey;
#pragma unroll
    for (int off = 16; off > 0; off >>= 1) {
        sx += __shfl_xor_sync(0xffffffffu, sx, off);
        sy += __shfl_xor_sync(0xffffffffu, sy, off);
    }
    return pk2(__fdividef(ex, sx), __fdividef(ey, sy));
}

__global__ void __launch_bounds__(NTHREADS, 1) gcn_kernel(
    const float* __restrict__ x,
    const float* __restrict__ c1w, const float* __restrict__ c1b,
    const float* __restrict__ g1,  const float* __restrict__ be1,
    const float* __restrict__ m1,  const float* __restrict__ v1,
    const float* __restrict__ c2w, const float* __restrict__ c2b,
    const float* __restrict__ g2,  const float* __restrict__ be2,
    const float* __restrict__ m2,  const float* __restrict__ v2,
    const float* __restrict__ lw,  const float* __restrict__ lb,
    float* __restrict__ out, int B)
{
    extern __shared__ ull smu[];
    ull*   w1P  = smu;                 // [k][32] packed (w,w)
    ull*   w2P  = w1P + W1P_U;
    float* linT = (float*)(w2P + W2P_U);   // [q][j][32]
    float* sb1  = linT + LINT_F;
    float* sb2  = sb1 + 32;
    float* ss1  = sb2 + 32;
    float* sbb1 = ss1 + 32;
    float* ss2  = sbb1 + 32;
    float* sbb2 = ss2 + 32;
    float* slb  = sbb2 + 32;           // 16 floats (13 used)
    ull*   scratch = (ull*)(slb + 16);

    const int tid = threadIdx.x;

    // ---- cooperative weight staging (transposed, pre-packed (w,w)) ----
    for (int i = tid; i < W1P_U; i += NTHREADS) {
        int k = i >> 5, o = i & 31;
        float w = c1w[o * 275 + k];
        w1P[i] = pk2(w, w);
    }
    for (int i = tid; i < W2P_U; i += NTHREADS) {
        int k = i >> 5, o = i & 31;
        float w = c2w[o * 160 + k];
        w2P[i] = pk2(w, w);
    }
    for (int i = tid; i < LINT_F; i += NTHREADS) {
        int n = i & 31, tj = i >> 5;
        int j = tj % 13, q = tj / 13;
        linT[i] = lw[j * 384 + n * 12 + q];
    }
    if (tid < 32) {
        sb1[tid] = c1b[tid];
        sb2[tid] = c2b[tid];
        float inv1 = g1[tid] / sqrtf(v1[tid] + 1e-5f);
        ss1[tid] = inv1; sbb1[tid] = be1[tid] - m1[tid] * inv1;
        float inv2 = g2[tid] / sqrtf(v2[tid] + 1e-5f);
        ss2[tid] = inv2; sbb2[tid] = be2[tid] - m2[tid] * inv2;
    }
    if (tid < 13) slb[tid] = lb[tid];
    __syncthreads();

    const int warp = tid >> 5, lane = tid & 31;
    const int b = blockIdx.x * WARPS_PER_CTA + warp;
    if (b >= B) return;

    ull* scw = scratch + warp * SCRATCH_U;
    // phase-overlapped layouts (ull offsets within scw):
    ull* xpad2 = scw;            // [25][36]  (900)   conv1 input, packed (xa,na)
    ull* hsh2  = scw;            // [32][26]  (832)   layer-1 h rows (aliases xpad2)
    ull* ppad2 = scw;            // [32][16]  (512)   layer-2 padded input
    ull* cshN  = scw + 512;      // [32][12]  (384)   conv2 out rows (xa,na)

    // ---- stage input, circularly padded, packed (xa, na) ----
    const float* xb = x + (size_t)b * 1250;
    for (int i = lane; i < 900; i += 32) {
        int p = i % 36, ck = i / 36;     // ck = c*5 + h
        float vx = 0.f, vy = 0.f;
        if (p < 35) {
            int wsrc = (p + 20) % 25;    // padded p -> orig (p-5) mod 25
            vx = xb[ck * 50 + wsrc];
            vy = xb[ck * 50 + 25 + wsrc];
        }
        xpad2[i] = pk2(vx, vy);
    }
    __syncwarp();

    // ======== LAYER 1: conv1 (both branches packed) ========
    ull acc[25];
    {
        float bv = sb1[lane];
        ull bia = pk2(bv, bv);
#pragma unroll
        for (int w = 0; w < 25; w++) acc[w] = bia;
    }
#pragma unroll 1
    for (int ck = 0; ck < 25; ck++) {
        const ulonglong2* row2 = (const ulonglong2*)(xpad2 + ck * 36);
        ull xr[36];
#pragma unroll
        for (int q = 0; q < 18; q++) {
            ulonglong2 t = row2[q];
            xr[2*q] = t.x; xr[2*q+1] = t.y;
        }
        ull wr[11];
        const ull* wp = w1P + ck * 11 * 32 + lane;
#pragma unroll
        for (int kw = 0; kw < 11; kw++) wr[kw] = wp[kw * 32];
#pragma unroll
        for (int kw = 0; kw < 11; kw++)
#pragma unroll
            for (int w = 0; w < 25; w++)
                acc[w] = ffma2(wr[kw], xr[w + kw], acc[w]);
    }

    // h rows (with bias) to warp-local shared, packed
#pragma unroll
    for (int f = 0; f < 25; f++) hsh2[lane * 26 + f] = acc[f];
    __syncwarp();

    // ---- attention 1, STREAMED per column m: dot -> softmax -> AV ----
    ull o1[25];
#pragma unroll
    for (int f = 0; f < 25; f++) o1[f] = 0;
#pragma unroll 4
    for (int m = 0; m < 32; m++) {
        const ull* hm = hsh2 + m * 26;
        const ulonglong2* hm2 = (const ulonglong2*)hm;
        ull p0 = 0, p1 = 0;
#pragma unroll
        for (int q = 0; q < 12; q++) {
            ulonglong2 t = hm2[q];
            p0 = ffma2(acc[2*q],   t.x, p0);
            p1 = ffma2(acc[2*q+1], t.y, p1);
        }
        p0 = fadd2(p0, p1);
        p0 = ffma2(acc[24], hm[24], p0);
        float sx, sy; up2(p0, sx, sy);
        ull a = softmax_col(lrelu(sx), lrelu(sy));
#pragma unroll
        for (int q = 0; q < 12; q++) {
            ulonglong2 t = hm2[q];
            o1[2*q]   = ffma2(a, t.x, o1[2*q]);
            o1[2*q+1] = ffma2(a, t.y, o1[2*q+1]);
        }
        o1[24] = ffma2(a, hm[24], o1[24]);
    }

    // ---- BN1 -> pairwise maxpool (drop f=24) -> relu ----
    ull p2[12];
    {
        float s1 = ss1[lane], b1v = sbb1[lane];
        ull sc = pk2(s1, s1), bo = pk2(b1v, b1v);
#pragma unroll
        for (int j = 0; j < 12; j++) {
            ull y0 = ffma2(o1[2*j],   sc, bo);
            ull y1 = ffma2(o1[2*j+1], sc, bo);
            float a0, c0, a1, c1;
            up2(y0, a0, c0); up2(y1, a1, c1);
            p2[j] = pk2(fmaxf(fmaxf(a0, a1), 0.f), fmaxf(fmaxf(c0, c1), 0.f));
        }
    }
    __syncwarp();   // scratch reuse boundary (hsh2 dead)

    // ======== LAYER 2 ========
    {
        ull* pr = ppad2 + lane * 16;     // circular pad 2 on width 12
#pragma unroll
        for (int j = 0; j < 12; j++) pr[2 + j] = p2[j];
        pr[0]  = p2[10]; pr[1]  = p2[11];
        pr[14] = p2[0];  pr[15] = p2[1];
    }
    __syncwarp();

    // conv2: 32 in-channels, 5 taps, width 12, packed branches
    ull a2[12];
    {
        float bv = sb2[lane];
        ull bia = pk2(bv, bv);
#pragma unroll
        for (int w = 0; w < 12; w++) a2[w] = bia;
    }
#pragma unroll 1
    for (int i = 0; i < 32; i++) {
        const ulonglong2* pr2 = (const ulonglong2*)(ppad2 + i * 16);
        ull prr[16];
#pragma unroll
        for (int q = 0; q < 8; q++) {
            ulonglong2 t = pr2[q];
            prr[2*q] = t.x; prr[2*q+1] = t.y;
        }
        ull wr[5];
        const ull* wp = w2P + i * 5 * 32 + lane;
#pragma unroll
        for (int kw = 0; kw < 5; kw++) wr[kw] = wp[kw * 32];
#pragma unroll
        for (int kw = 0; kw < 5; kw++)
#pragma unroll
            for (int w = 0; w < 12; w++)
                a2[w] = ffma2(wr[kw], prr[w + kw], a2[w]);
    }

    // store conv2 rows (xa,na); own swapped copy kept in regs
    ull c2s[12];
    {
        ull* cN = cshN + lane * 12;
#pragma unroll
        for (int w = 0; w < 12; w++) {
            cN[w] = a2[w];
            c2s[w] = swp(a2[w]);
        }
    }
    __syncwarp();

    // ---- attention 2 (cross branches), STREAMED: att = (att_n2, att_x2) ----
    ull o2[12];
#pragma unroll
    for (int f = 0; f < 12; f++) o2[f] = 0;
#pragma unroll 4
    for (int m = 0; m < 32; m++) {
        const ulonglong2* hm2 = (const ulonglong2*)(cshN + m * 12);
        ull hv[12];
        ull p0 = 0, p1 = 0;
#pragma unroll
        for (int q = 0; q < 6; q++) {
            ulonglong2 t = hm2[q];
            hv[2*q] = t.x; hv[2*q+1] = t.y;
            p0 = ffma2(c2s[2*q],   t.x, p0);
            p1 = ffma2(c2s[2*q+1], t.y, p1);
        }
        p0 = fadd2(p0, p1);
        float sx, sy; up2(p0, sx, sy);
        ull a = softmax_col(lrelu(sx), lrelu(sy));
        // AV against swapped rows: o2 = (n2_val, x2_val)
#pragma unroll
        for (int f = 0; f < 12; f++)
            o2[f] = ffma2(a, swp(hv[f]), o2[f]);
    }

    // BN2 -> maxpool -> relu; unpack into x2p / n2p
    float opx[6], opn[6];
    {
        float s2 = ss2[lane], b2v = sbb2[lane];
        ull sc = pk2(s2, s2), bo = pk2(b2v, b2v);
#pragma unroll
        for (int j = 0; j < 6; j++) {
            ull y0 = ffma2(o2[2*j],   sc, bo);
            ull y1 = ffma2(o2[2*j+1], sc, bo);
            float n0, x0, n1, x1;
            up2(y0, n0, x0); up2(y1, n1, x1);
            opx[j] = fmaxf(fmaxf(x0, x1), 0.f);
            opn[j] = fmaxf(fmaxf(n0, n1), 0.f);
        }
    }

    // ======== final linear: flat[n*12+q], q<6 -> x2p, q>=6 -> n2p ========
    float part[13];
#pragma unroll
    for (int j = 0; j < 13; j++) part[j] = 0.f;
#pragma unroll
    for (int q = 0; q < 12; q++) {
        float v = (q < 6) ? opx[q] : opn[q - 6];
        const float* wrow = linT + q * 13 * 32 + lane;
#pragma unroll
        for (int j = 0; j < 13; j++) part[j] = fmaf(v, wrow[j * 32], part[j]);
    }
#pragma unroll
    for (int off = 16; off > 0; off >>= 1)
#pragma unroll
        for (int j = 0; j < 13; j++)
            part[j] += __shfl_xor_sync(0xffffffffu, part[j], off);

    if (lane == 0) {
#pragma unroll
        for (int j = 0; j < 13; j++)
            out[(size_t)b * 13 + j] = part[j] + slb[j];
    }
}

extern "C" void kernel_launch(void* const* d_in, const int* in_sizes, int n_in,
                              void* d_out, int out_size) {
    const float* x   = (const float*)d_in[0];
    const float* c1w = (const float*)d_in[1];
    const float* c1b = (const float*)d_in[2];
    const float* g1  = (const float*)d_in[3];
    const float* be1 = (const float*)d_in[4];
    const float* m1  = (const float*)d_in[5];
    const float* v1  = (const float*)d_in[6];
    const float* c2w = (const float*)d_in[7];
    const float* c2b = (const float*)d_in[8];
    const float* g2  = (const float*)d_in[9];
    const float* be2 = (const float*)d_in[10];
    const float* m2  = (const float*)d_in[11];
    const float* v2  = (const float*)d_in[12];
    const float* lw  = (const float*)d_in[13];
    const float* lb  = (const float*)d_in[14];
    float* out = (float*)d_out;

    int B = in_sizes[0] / 1250;   // 16384
    int grid = (B + WARPS_PER_CTA - 1) / WARPS_PER_CTA;

    cudaFuncSetAttribute(gcn_kernel, cudaFuncAttributeMaxDynamicSharedMemorySize, SMEM_BYTES);
    gcn_kernel<<<grid, NTHREADS, SMEM_BYTES>>>(x, c1w, c1b, g1, be1, m1, v1,
                                               c2w, c2b, g2, be2, m2, v2,
                                               lw, lb, out, B);
}

// round 13
// speedup vs baseline: 1.6355x; 1.0056x over previous
#include <cuda_runtime.h>

#define WARPS_PER_CTA 12
#define NTHREADS (WARPS_PER_CTA * 32)

#define W1P_U 8800            // ull [275][32] packed (w,w), lane-major
#define W2P_U 5120            // ull [160][32] packed
#define LIN2_U 2496           // ull [6][13][32] packed (w_q, w_{q+6})
#define CONST_F (6*32 + 16)

#define SCRATCH_U 904         // ull slots per warp (7232 B)
#define SMEM_BYTES ((W1P_U + W2P_U + LIN2_U) * 8 + CONST_F * 4 + WARPS_PER_CTA * SCRATCH_U * 8)

typedef unsigned long long ull;

__device__ __forceinline__ ull pk2(float x, float y) {
    ull r; asm("mov.b64 %0, {%1,%2};" : "=l"(r) : "f"(x), "f"(y)); return r;
}
__device__ __forceinline__ void up2(ull v, float& x, float& y) {
    asm("mov.b64 {%0,%1}, %2;" : "=f"(x), "=f"(y) : "l"(v));
}
__device__ __forceinline__ ull swp(ull v) {
    float a, b; up2(v, a, b); return pk2(b, a);
}
__device__ __forceinline__ ull ffma2(ull a, ull b, ull c) {
    ull d; asm("fma.rn.f32x2 %0, %1, %2, %3;" : "=l"(d) : "l"(a), "l"(b), "l"(c)); return d;
}
__device__ __forceinline__ ull fadd2(ull a, ull b) {
    ull d; asm("add.rn.f32x2 %0, %1, %2;" : "=l"(d) : "l"(a), "l"(b)); return d;
}
// branch-free leaky relu on the fma/alu pipes (no predicate)
__device__ __forceinline__ float lrelu(float v) { return fmaxf(v, 0.2f * v); }

// warp-max of a float via order-preserving integer map + redux.sync.max.u32
__device__ __forceinline__ unsigned redux_max_u32(unsigned v) {
    unsigned r; asm("redux.sync.max.u32 %0, %1, 0xffffffff;" : "=r"(r) : "r"(v)); return r;
}
__device__ __forceinline__ float warp_max_f(float f) {
    unsigned b = __float_as_uint(f);
    unsigned u = b ^ ((unsigned)((int)b >> 31) | 0x80000000u);     // monotone encode
    unsigned m = redux_max_u32(u);
    unsigned mb = m ^ ((unsigned)((int)(~m) >> 31) | 0x80000000u); // decode
    return __uint_as_float(mb);
}

// lane-softmax for ONE packed column: (ax, ay) raw leaky'd scores ->
// packed normalized attention weight for this lane.
__device__ __forceinline__ ull softmax_col(float ax, float ay) {
    float mx = warp_max_f(ax), my = warp_max_f(ay);
    float ex = __expf(ax - mx), ey = __expf(ay - my);
    float sx = ex, sy = ey;
#pragma unroll
    for (int off = 16; off > 0; off >>= 1) {
        sx += __shfl_xor_sync(0xffffffffu, sx, off);
        sy += __shfl_xor_sync(0xffffffffu, sy, off);
    }
    return pk2(__fdividef(ex, sx), __fdividef(ey, sy));
}

__global__ void __launch_bounds__(NTHREADS, 1) gcn_kernel(
    const float* __restrict__ x,
    const float* __restrict__ c1w, const float* __restrict__ c1b,
    const float* __restrict__ g1,  const float* __restrict__ be1,
    const float* __restrict__ m1,  const float* __restrict__ v1,
    const float* __restrict__ c2w, const float* __restrict__ c2b,
    const float* __restrict__ g2,  const float* __restrict__ be2,
    const float* __restrict__ m2,  const float* __restrict__ v2,
    const float* __restrict__ lw,  const float* __restrict__ lb,
    float* __restrict__ out, int B)
{
    extern __shared__ ull smu[];
    ull*   w1P  = smu;                 // [k][32] packed (w,w)
    ull*   w2P  = w1P + W1P_U;
    ull*   lin2 = w2P + W2P_U;         // [q][j][32] packed (w_q, w_{q+6})
    float* sb1  = (float*)(lin2 + LIN2_U);
    float* sb2  = sb1 + 32;
    float* ss1  = sb2 + 32;
    float* sbb1 = ss1 + 32;
    float* ss2  = sbb1 + 32;
    float* sbb2 = ss2 + 32;
    float* slb  = sbb2 + 32;           // 16 floats (13 used)
    ull*   scratch = (ull*)(slb + 16);

    const int tid = threadIdx.x;

    // ---- cooperative weight staging (transposed, pre-packed) ----
    for (int i = tid; i < W1P_U; i += NTHREADS) {
        int k = i >> 5, o = i & 31;
        float w = c1w[o * 275 + k];
        w1P[i] = pk2(w, w);
    }
    for (int i = tid; i < W2P_U; i += NTHREADS) {
        int k = i >> 5, o = i & 31;
        float w = c2w[o * 160 + k];
        w2P[i] = pk2(w, w);
    }
    for (int i = tid; i < LIN2_U; i += NTHREADS) {
        int n = i & 31, tj = i >> 5;
        int j = tj % 13, q = tj / 13;          // q in 0..5
        lin2[i] = pk2(lw[j * 384 + n * 12 + q], lw[j * 384 + n * 12 + q + 6]);
    }
    if (tid < 32) {
        sb1[tid] = c1b[tid];
        sb2[tid] = c2b[tid];
        float inv1 = g1[tid] / sqrtf(v1[tid] + 1e-5f);
        ss1[tid] = inv1; sbb1[tid] = be1[tid] - m1[tid] * inv1;
        float inv2 = g2[tid] / sqrtf(v2[tid] + 1e-5f);
        ss2[tid] = inv2; sbb2[tid] = be2[tid] - m2[tid] * inv2;
    }
    if (tid < 13) slb[tid] = lb[tid];
    __syncthreads();

    const int warp = tid >> 5, lane = tid & 31;
    const int b = blockIdx.x * WARPS_PER_CTA + warp;
    if (b >= B) return;

    ull* scw = scratch + warp * SCRATCH_U;
    // phase-overlapped layouts (ull offsets within scw):
    ull* xpad2 = scw;            // [25][36]  (900)   conv1 input, packed (xa,na)
    ull* hsh2  = scw;            // [32][26]  (832)   layer-1 h rows (aliases xpad2)
    ull* ppad2 = scw;            // [32][16]  (512)   layer-2 padded input
    ull* cshN  = scw + 512;      // [32][12]  (384)   conv2 out rows (xa,na)

    // ---- stage input, circularly padded, packed (xa, na) ----
    const float* xb = x + (size_t)b * 1250;
    for (int i = lane; i < 900; i += 32) {
        int p = i % 36, ck = i / 36;     // ck = c*5 + h
        float vx = 0.f, vy = 0.f;
        if (p < 35) {
            int wsrc = (p + 20) % 25;    // padded p -> orig (p-5) mod 25
            vx = xb[ck * 50 + wsrc];
            vy = xb[ck * 50 + 25 + wsrc];
        }
        xpad2[i] = pk2(vx, vy);
    }
    __syncwarp();

    // ======== LAYER 1: conv1 (both branches packed) ========
    ull acc[25];
    {
        float bv = sb1[lane];
        ull bia = pk2(bv, bv);
#pragma unroll
        for (int w = 0; w < 25; w++) acc[w] = bia;
    }
#pragma unroll 1
    for (int ck = 0; ck < 25; ck++) {
        const ulonglong2* row2 = (const ulonglong2*)(xpad2 + ck * 36);
        ull xr[36];
#pragma unroll
        for (int q = 0; q < 18; q++) {
            ulonglong2 t = row2[q];
            xr[2*q] = t.x; xr[2*q+1] = t.y;
        }
        ull wr[11];
        const ull* wp = w1P + ck * 11 * 32 + lane;
#pragma unroll
        for (int kw = 0; kw < 11; kw++) wr[kw] = wp[kw * 32];
#pragma unroll
        for (int kw = 0; kw < 11; kw++)
#pragma unroll
            for (int w = 0; w < 25; w++)
                acc[w] = ffma2(wr[kw], xr[w + kw], acc[w]);
    }

    // h rows (with bias) to warp-local shared, packed
#pragma unroll
    for (int f = 0; f < 25; f++) hsh2[lane * 26 + f] = acc[f];
    __syncwarp();

    // ---- attention 1, STREAMED per column m: dot -> softmax -> AV ----
    ull o1[25];
#pragma unroll
    for (int f = 0; f < 25; f++) o1[f] = 0;
#pragma unroll 4
    for (int m = 0; m < 32; m++) {
        const ull* hm = hsh2 + m * 26;
        const ulonglong2* hm2 = (const ulonglong2*)hm;
        ull p0 = 0, p1 = 0;
#pragma unroll
        for (int q = 0; q < 12; q++) {
            ulonglong2 t = hm2[q];
            p0 = ffma2(acc[2*q],   t.x, p0);
            p1 = ffma2(acc[2*q+1], t.y, p1);
        }
        p0 = fadd2(p0, p1);
        p0 = ffma2(acc[24], hm[24], p0);
        float sx, sy; up2(p0, sx, sy);
        ull a = softmax_col(lrelu(sx), lrelu(sy));
#pragma unroll
        for (int q = 0; q < 12; q++) {
            ulonglong2 t = hm2[q];
            o1[2*q]   = ffma2(a, t.x, o1[2*q]);
            o1[2*q+1] = ffma2(a, t.y, o1[2*q+1]);
        }
        o1[24] = ffma2(a, hm[24], o1[24]);
    }

    // ---- BN1 -> pairwise maxpool (drop f=24) -> relu ----
    ull p2[12];
    {
        float s1 = ss1[lane], b1v = sbb1[lane];
        ull sc = pk2(s1, s1), bo = pk2(b1v, b1v);
#pragma unroll
        for (int j = 0; j < 12; j++) {
            ull y0 = ffma2(o1[2*j],   sc, bo);
            ull y1 = ffma2(o1[2*j+1], sc, bo);
            float a0, c0, a1, c1;
            up2(y0, a0, c0); up2(y1, a1, c1);
            p2[j] = pk2(fmaxf(fmaxf(a0, a1), 0.f), fmaxf(fmaxf(c0, c1), 0.f));
        }
    }
    __syncwarp();   // scratch reuse boundary (hsh2 dead)

    // ======== LAYER 2 ========
    {
        ull* pr = ppad2 + lane * 16;     // circular pad 2 on width 12
#pragma unroll
        for (int j = 0; j < 12; j++) pr[2 + j] = p2[j];
        pr[0]  = p2[10]; pr[1]  = p2[11];
        pr[14] = p2[0];  pr[15] = p2[1];
    }
    __syncwarp();

    // conv2: 32 in-channels, 5 taps, width 12, packed branches
    ull a2[12];
    {
        float bv = sb2[lane];
        ull bia = pk2(bv, bv);
#pragma unroll
        for (int w = 0; w < 12; w++) a2[w] = bia;
    }
#pragma unroll 1
    for (int i = 0; i < 32; i++) {
        const ulonglong2* pr2 = (const ulonglong2*)(ppad2 + i * 16);
        ull prr[16];
#pragma unroll
        for (int q = 0; q < 8; q++) {
            ulonglong2 t = pr2[q];
            prr[2*q] = t.x; prr[2*q+1] = t.y;
        }
        ull wr[5];
        const ull* wp = w2P + i * 5 * 32 + lane;
#pragma unroll
        for (int kw = 0; kw < 5; kw++) wr[kw] = wp[kw * 32];
#pragma unroll
        for (int kw = 0; kw < 5; kw++)
#pragma unroll
            for (int w = 0; w < 12; w++)
                a2[w] = ffma2(wr[kw], prr[w + kw], a2[w]);
    }

    // store conv2 rows (xa,na); own swapped copy kept in regs
    ull c2s[12];
    {
        ull* cN = cshN + lane * 12;
#pragma unroll
        for (int w = 0; w < 12; w++) {
            cN[w] = a2[w];
            c2s[w] = swp(a2[w]);
        }
    }
    __syncwarp();

    // ---- attention 2 (cross branches), STREAMED ----
    // dot with own swapped rows gives a = (att_n2, att_x2).
    // AV trick: o2s[f] = sum_m swp(a_m) (x) h_m[f]  ==  (x2_val, n2_val)
    // (identity: a (x) swp(h) = swp( swp(a) (x) h )) -> one swap per m, none per f.
    ull o2[12];
#pragma unroll
    for (int f = 0; f < 12; f++) o2[f] = 0;
#pragma unroll 4
    for (int m = 0; m < 32; m++) {
        const ulonglong2* hm2 = (const ulonglong2*)(cshN + m * 12);
        ull hv[12];
        ull p0 = 0, p1 = 0;
#pragma unroll
        for (int q = 0; q < 6; q++) {
            ulonglong2 t = hm2[q];
            hv[2*q] = t.x; hv[2*q+1] = t.y;
            p0 = ffma2(c2s[2*q],   t.x, p0);
            p1 = ffma2(c2s[2*q+1], t.y, p1);
        }
        p0 = fadd2(p0, p1);
        float sx, sy; up2(p0, sx, sy);
        ull a = swp(softmax_col(lrelu(sx), lrelu(sy)));   // (att_x2, att_n2)
#pragma unroll
        for (int f = 0; f < 12; f++)
            o2[f] = ffma2(a, hv[f], o2[f]);
    }

    // BN2 -> maxpool -> relu; o2 components are (x2_val, n2_val)
    float opx[6], opn[6];
    {
        float s2 = ss2[lane], b2v = sbb2[lane];
        ull sc = pk2(s2, s2), bo = pk2(b2v, b2v);
#pragma unroll
        for (int j = 0; j < 6; j++) {
            ull y0 = ffma2(o2[2*j],   sc, bo);
            ull y1 = ffma2(o2[2*j+1], sc, bo);
            float x0, n0, x1, n1;
            up2(y0, x0, n0); up2(y1, x1, n1);
            opx[j] = fmaxf(fmaxf(x0, x1), 0.f);
            opn[j] = fmaxf(fmaxf(n0, n1), 0.f);
        }
    }

    // ======== final linear (packed over branch pairs) ========
    // flat[n*12+q] = q<6 ? x2p[q] : n2p[q-6]; lin2[q][j][lane] = (w_q, w_{q+6})
    ull part[13];
#pragma unroll
    for (int j = 0; j < 13; j++) part[j] = 0;
#pragma unroll
    for (int q = 0; q < 6; q++) {
        ull v = pk2(opx[q], opn[q]);
        const ull* wrow = lin2 + q * 13 * 32 + lane;
#pragma unroll
        for (int j = 0; j < 13; j++) part[j] = ffma2(v, wrow[j * 32], part[j]);
    }
    float ps[13];
#pragma unroll
    for (int j = 0; j < 13; j++) {
        float a, bq; up2(part[j], a, bq);
        ps[j] = a + bq;
    }
#pragma unroll
    for (int off = 16; off > 0; off >>= 1)
#pragma unroll
        for (int j = 0; j < 13; j++)
            ps[j] += __shfl_xor_sync(0xffffffffu, ps[j], off);

    if (lane == 0) {
#pragma unroll
        for (int j = 0; j < 13; j++)
            out[(size_t)b * 13 + j] = ps[j] + slb[j];
    }
}

extern "C" void kernel_launch(void* const* d_in, const int* in_sizes, int n_in,
                              void* d_out, int out_size) {
    const float* x   = (const float*)d_in[0];
    const float* c1w = (const float*)d_in[1];
    const float* c1b = (const float*)d_in[2];
    const float* g1  = (const float*)d_in[3];
    const float* be1 = (const float*)d_in[4];
    const float* m1  = (const float*)d_in[5];
    const float* v1  = (const float*)d_in[6];
    const float* c2w = (const float*)d_in[7];
    const float* c2b = (const float*)d_in[8];
    const float* g2  = (const float*)d_in[9];
    const float* be2 = (const float*)d_in[10];
    const float* m2  = (const float*)d_in[11];
    const float* v2  = (const float*)d_in[12];
    const float* lw  = (const float*)d_in[13];
    const float* lb  = (const float*)d_in[14];
    float* out = (float*)d_out;

    int B = in_sizes[0] / 1250;   // 16384
    int grid = (B + WARPS_PER_CTA - 1) / WARPS_PER_CTA;

    cudaFuncSetAttribute(gcn_kernel, cudaFuncAttributeMaxDynamicSharedMemorySize, SMEM_BYTES);
    gcn_kernel<<<grid, NTHREADS, SMEM_BYTES>>>(x, c1w, c1b, g1, be1, m1, v1,
                                               c2w, c2b, g2, be2, m2, v2,
                                               lw, lb, out, B);
}

// round 15
// speedup vs baseline: 1.6709x; 1.0216x over previous
#include <cuda_runtime.h>

#define WARPS_PER_CTA 12
#define NTHREADS (WARPS_PER_CTA * 32)

#define W1P_U 8800            // ull [275][32] packed (w,w), lane-major
#define W2P_U 5120            // ull [160][32] packed
#define LIN2_U 2496           // ull [6][13][32] packed (w_q, w_{q+6})
#define CONST_F (6*32 + 16)

#define SCRATCH_U 904         // ull slots per warp (7232 B)
#define SMEM_BYTES ((W1P_U + W2P_U + LIN2_U) * 8 + CONST_F * 4 + WARPS_PER_CTA * SCRATCH_U * 8)

typedef unsigned long long ull;

__device__ __forceinline__ ull pk2(float x, float y) {
    ull r; asm("mov.b64 %0, {%1,%2};" : "=l"(r) : "f"(x), "f"(y)); return r;
}
__device__ __forceinline__ void up2(ull v, float& x, float& y) {
    asm("mov.b64 {%0,%1}, %2;" : "=f"(x), "=f"(y) : "l"(v));
}
__device__ __forceinline__ ull swp(ull v) {
    float a, b; up2(v, a, b); return pk2(b, a);
}
__device__ __forceinline__ ull ffma2(ull a, ull b, ull c) {
    ull d; asm("fma.rn.f32x2 %0, %1, %2, %3;" : "=l"(d) : "l"(a), "l"(b), "l"(c)); return d;
}
__device__ __forceinline__ ull fadd2(ull a, ull b) {
    ull d; asm("add.rn.f32x2 %0, %1, %2;" : "=l"(d) : "l"(a), "l"(b)); return d;
}
// branch-free leaky relu on the fma/alu pipes (no predicate)
__device__ __forceinline__ float lrelu(float v) { return fmaxf(v, 0.2f * v); }

// integer warp reductions (single REDUX instruction; fp32 redux doesn't exist on sm_103)
__device__ __forceinline__ unsigned redux_max_u32(unsigned v) {
    unsigned r; asm("redux.sync.max.u32 %0, %1, 0xffffffff;" : "=r"(r) : "r"(v)); return r;
}
__device__ __forceinline__ unsigned redux_add_u32(unsigned v) {
    unsigned r; asm("redux.sync.add.u32 %0, %1, 0xffffffff;" : "=r"(r) : "r"(v)); return r;
}
__device__ __forceinline__ float warp_max_f(float f) {
    unsigned b = __float_as_uint(f);
    unsigned u = b ^ ((unsigned)((int)b >> 31) | 0x80000000u);     // monotone encode
    unsigned m = redux_max_u32(u);
    unsigned mb = m ^ ((unsigned)((int)(~m) >> 31) | 0x80000000u); // decode
    return __uint_as_float(mb);
}

// lane-softmax for ONE packed column: (ax, ay) raw leaky'd scores ->
// packed normalized attention weight for this lane.
// Sum via fixed-point integer REDUX: terms are in (0,1] post max-subtraction,
// scaled by 2^25; 32 terms * 2^25 = 2^30 < 2^32. Quantization rel-err ~5e-7.
__device__ __forceinline__ ull softmax_col(float ax, float ay) {
    const float S = 33554432.f;   // 2^25
    float mx = warp_max_f(ax), my = warp_max_f(ay);
    float exS = __expf(ax - mx) * S, eyS = __expf(ay - my) * S;
    unsigned sxu = redux_add_u32(__float2uint_rn(exS));
    unsigned syu = redux_add_u32(__float2uint_rn(eyS));
    return pk2(__fdividef(exS, (float)sxu), __fdividef(eyS, (float)syu));
}

__global__ void __launch_bounds__(NTHREADS, 1) gcn_kernel(
    const float* __restrict__ x,
    const float* __restrict__ c1w, const float* __restrict__ c1b,
    const float* __restrict__ g1,  const float* __restrict__ be1,
    const float* __restrict__ m1,  const float* __restrict__ v1,
    const float* __restrict__ c2w, const float* __restrict__ c2b,
    const float* __restrict__ g2,  const float* __restrict__ be2,
    const float* __restrict__ m2,  const float* __restrict__ v2,
    const float* __restrict__ lw,  const float* __restrict__ lb,
    float* __restrict__ out, int B)
{
    extern __shared__ ull smu[];
    ull*   w1P  = smu;                 // [k][32] packed (w,w)
    ull*   w2P  = w1P + W1P_U;
    ull*   lin2 = w2P + W2P_U;         // [q][j][32] packed (w_q, w_{q+6})
    float* sb1  = (float*)(lin2 + LIN2_U);
    float* sb2  = sb1 + 32;
    float* ss1  = sb2 + 32;
    float* sbb1 = ss1 + 32;
    float* ss2  = sbb1 + 32;
    float* sbb2 = ss2 + 32;
    float* slb  = sbb2 + 32;           // 16 floats (13 used)
    ull*   scratch = (ull*)(slb + 16);

    const int tid = threadIdx.x;

    // ---- cooperative weight staging (transposed, pre-packed) ----
    for (int i = tid; i < W1P_U; i += NTHREADS) {
        int k = i >> 5, o = i & 31;
        float w = c1w[o * 275 + k];
        w1P[i] = pk2(w, w);
    }
    for (int i = tid; i < W2P_U; i += NTHREADS) {
        int k = i >> 5, o = i & 31;
        float w = c2w[o * 160 + k];
        w2P[i] = pk2(w, w);
    }
    for (int i = tid; i < LIN2_U; i += NTHREADS) {
        int n = i & 31, tj = i >> 5;
        int j = tj % 13, q = tj / 13;          // q in 0..5
        lin2[i] = pk2(lw[j * 384 + n * 12 + q], lw[j * 384 + n * 12 + q + 6]);
    }
    if (tid < 32) {
        sb1[tid] = c1b[tid];
        sb2[tid] = c2b[tid];
        float inv1 = g1[tid] / sqrtf(v1[tid] + 1e-5f);
        ss1[tid] = inv1; sbb1[tid] = be1[tid] - m1[tid] * inv1;
        float inv2 = g2[tid] / sqrtf(v2[tid] + 1e-5f);
        ss2[tid] = inv2; sbb2[tid] = be2[tid] - m2[tid] * inv2;
    }
    if (tid < 13) slb[tid] = lb[tid];
    __syncthreads();

    const int warp = tid >> 5, lane = tid & 31;
    const int b = blockIdx.x * WARPS_PER_CTA + warp;
    if (b >= B) return;

    ull* scw = scratch + warp * SCRATCH_U;
    // phase-overlapped layouts (ull offsets within scw):
    ull* xpad2 = scw;            // [25][36]  (900)   conv1 input, packed (xa,na)
    ull* hsh2  = scw;            // [32][26]  (832)   layer-1 h rows (aliases xpad2)
    ull* ppad2 = scw;            // [32][16]  (512)   layer-2 padded input
    ull* cshN  = scw + 512;      // [32][12]  (384)   conv2 out rows (xa,na)

    // ---- stage input, circularly padded, packed (xa, na) ----
    const float* xb = x + (size_t)b * 1250;
    for (int i = lane; i < 900; i += 32) {
        int p = i % 36, ck = i / 36;     // ck = c*5 + h
        float vx = 0.f, vy = 0.f;
        if (p < 35) {
            int wsrc = (p + 20) % 25;    // padded p -> orig (p-5) mod 25
            vx = xb[ck * 50 + wsrc];
            vy = xb[ck * 50 + 25 + wsrc];
        }
        xpad2[i] = pk2(vx, vy);
    }
    __syncwarp();

    // ======== LAYER 1: conv1 (both branches packed) ========
    ull acc[25];
    {
        float bv = sb1[lane];
        ull bia = pk2(bv, bv);
#pragma unroll
        for (int w = 0; w < 25; w++) acc[w] = bia;
    }
#pragma unroll 1
    for (int ck = 0; ck < 25; ck++) {
        const ulonglong2* row2 = (const ulonglong2*)(xpad2 + ck * 36);
        ull xr[36];
#pragma unroll
        for (int q = 0; q < 18; q++) {
            ulonglong2 t = row2[q];
            xr[2*q] = t.x; xr[2*q+1] = t.y;
        }
        ull wr[11];
        const ull* wp = w1P + ck * 11 * 32 + lane;
#pragma unroll
        for (int kw = 0; kw < 11; kw++) wr[kw] = wp[kw * 32];
#pragma unroll
        for (int kw = 0; kw < 11; kw++)
#pragma unroll
            for (int w = 0; w < 25; w++)
                acc[w] = ffma2(wr[kw], xr[w + kw], acc[w]);
    }

    // h rows (with bias) to warp-local shared, packed
#pragma unroll
    for (int f = 0; f < 25; f++) hsh2[lane * 26 + f] = acc[f];
    __syncwarp();

    // ---- attention 1, STREAMED per column m: dot -> softmax -> AV ----
    ull o1[25];
#pragma unroll
    for (int f = 0; f < 25; f++) o1[f] = 0;
#pragma unroll 4
    for (int m = 0; m < 32; m++) {
        const ull* hm = hsh2 + m * 26;
        const ulonglong2* hm2 = (const ulonglong2*)hm;
        ull p0 = 0, p1 = 0;
#pragma unroll
        for (int q = 0; q < 12; q++) {
            ulonglong2 t = hm2[q];
            p0 = ffma2(acc[2*q],   t.x, p0);
            p1 = ffma2(acc[2*q+1], t.y, p1);
        }
        p0 = fadd2(p0, p1);
        p0 = ffma2(acc[24], hm[24], p0);
        float sx, sy; up2(p0, sx, sy);
        ull a = softmax_col(lrelu(sx), lrelu(sy));
#pragma unroll
        for (int q = 0; q < 12; q++) {
            ulonglong2 t = hm2[q];
            o1[2*q]   = ffma2(a, t.x, o1[2*q]);
            o1[2*q+1] = ffma2(a, t.y, o1[2*q+1]);
        }
        o1[24] = ffma2(a, hm[24], o1[24]);
    }

    // ---- BN1 -> pairwise maxpool (drop f=24) -> relu ----
    ull p2[12];
    {
        float s1 = ss1[lane], b1v = sbb1[lane];
        ull sc = pk2(s1, s1), bo = pk2(b1v, b1v);
#pragma unroll
        for (int j = 0; j < 12; j++) {
            ull y0 = ffma2(o1[2*j],   sc, bo);
            ull y1 = ffma2(o1[2*j+1], sc, bo);
            float a0, c0, a1, c1;
            up2(y0, a0, c0); up2(y1, a1, c1);
            p2[j] = pk2(fmaxf(fmaxf(a0, a1), 0.f), fmaxf(fmaxf(c0, c1), 0.f));
        }
    }
    __syncwarp();   // scratch reuse boundary (hsh2 dead)

    // ======== LAYER 2 ========
    {
        ull* pr = ppad2 + lane * 16;     // circular pad 2 on width 12
#pragma unroll
        for (int j = 0; j < 12; j++) pr[2 + j] = p2[j];
        pr[0]  = p2[10]; pr[1]  = p2[11];
        pr[14] = p2[0];  pr[15] = p2[1];
    }
    __syncwarp();

    // conv2: 32 in-channels, 5 taps, width 12, packed branches
    ull a2[12];
    {
        float bv = sb2[lane];
        ull bia = pk2(bv, bv);
#pragma unroll
        for (int w = 0; w < 12; w++) a2[w] = bia;
    }
#pragma unroll 1
    for (int i = 0; i < 32; i++) {
        const ulonglong2* pr2 = (const ulonglong2*)(ppad2 + i * 16);
        ull prr[16];
#pragma unroll
        for (int q = 0; q < 8; q++) {
            ulonglong2 t = pr2[q];
            prr[2*q] = t.x; prr[2*q+1] = t.y;
        }
        ull wr[5];
        const ull* wp = w2P + i * 5 * 32 + lane;
#pragma unroll
        for (int kw = 0; kw < 5; kw++) wr[kw] = wp[kw * 32];
#pragma unroll
        for (int kw = 0; kw < 5; kw++)
#pragma unroll
            for (int w = 0; w < 12; w++)
                a2[w] = ffma2(wr[kw], prr[w + kw], a2[w]);
    }

    // store conv2 rows (xa,na); own swapped copy kept in regs
    ull c2s[12];
    {
        ull* cN = cshN + lane * 12;
#pragma unroll
        for (int w = 0; w < 12; w++) {
            cN[w] = a2[w];
            c2s[w] = swp(a2[w]);
        }
    }
    __syncwarp();

    // ---- attention 2 (cross branches), STREAMED ----
    // dot with own swapped rows gives a = (att_n2, att_x2).
    // AV trick: o2s[f] = sum_m swp(a_m) (x) h_m[f]  ==  (x2_val, n2_val)
    ull o2[12];
#pragma unroll
    for (int f = 0; f < 12; f++) o2[f] = 0;
#pragma unroll 4
    for (int m = 0; m < 32; m++) {
        const ulonglong2* hm2 = (const ulonglong2*)(cshN + m * 12);
        ull hv[12];
        ull p0 = 0, p1 = 0;
#pragma unroll
        for (int q = 0; q < 6; q++) {
            ulonglong2 t = hm2[q];
            hv[2*q] = t.x; hv[2*q+1] = t.y;
            p0 = ffma2(c2s[2*q],   t.x, p0);
            p1 = ffma2(c2s[2*q+1], t.y, p1);
        }
        p0 = fadd2(p0, p1);
        float sx, sy; up2(p0, sx, sy);
        ull a = swp(softmax_col(lrelu(sx), lrelu(sy)));   // (att_x2, att_n2)
#pragma unroll
        for (int f = 0; f < 12; f++)
            o2[f] = ffma2(a, hv[f], o2[f]);
    }

    // BN2 -> maxpool -> relu; o2 components are (x2_val, n2_val)
    float opx[6], opn[6];
    {
        float s2 = ss2[lane], b2v = sbb2[lane];
        ull sc = pk2(s2, s2), bo = pk2(b2v, b2v);
#pragma unroll
        for (int j = 0; j < 6; j++) {
            ull y0 = ffma2(o2[2*j],   sc, bo);
            ull y1 = ffma2(o2[2*j+1], sc, bo);
            float x0, n0, x1, n1;
            up2(y0, x0, n0); up2(y1, x1, n1);
            opx[j] = fmaxf(fmaxf(x0, x1), 0.f);
            opn[j] = fmaxf(fmaxf(n0, n1), 0.f);
        }
    }

    // ======== final linear (packed over branch pairs) ========
    ull part[13];
#pragma unroll
    for (int j = 0; j < 13; j++) part[j] = 0;
#pragma unroll
    for (int q = 0; q < 6; q++) {
        ull v = pk2(opx[q], opn[q]);
        const ull* wrow = lin2 + q * 13 * 32 + lane;
#pragma unroll
        for (int j = 0; j < 13; j++) part[j] = ffma2(v, wrow[j * 32], part[j]);
    }
    float ps[13];
#pragma unroll
    for (int j = 0; j < 13; j++) {
        float a, bq; up2(part[j], a, bq);
        ps[j] = a + bq;
    }
#pragma unroll
    for (int off = 16; off > 0; off >>= 1)
#pragma unroll
        for (int j = 0; j < 13; j++)
            ps[j] += __shfl_xor_sync(0xffffffffu, ps[j], off);

    if (lane == 0) {
#pragma unroll
        for (int j = 0; j < 13; j++)
            out[(size_t)b * 13 + j] = ps[j] + slb[j];
    }
}

extern "C" void kernel_launch(void* const* d_in, const int* in_sizes, int n_in,
                              void* d_out, int out_size) {
    const float* x   = (const float*)d_in[0];
    const float* c1w = (const float*)d_in[1];
    const float* c1b = (const float*)d_in[2];
    const float* g1  = (const float*)d_in[3];
    const float* be1 = (const float*)d_in[4];
    const float* m1  = (const float*)d_in[5];
    const float* v1  = (const float*)d_in[6];
    const float* c2w = (const float*)d_in[7];
    const float* c2b = (const float*)d_in[8];
    const float* g2  = (const float*)d_in[9];
    const float* be2 = (const float*)d_in[10];
    const float* m2  = (const float*)d_in[11];
    const float* v2  = (const float*)d_in[12];
    const float* lw  = (const float*)d_in[13];
    const float* lb  = (const float*)d_in[14];
    float* out = (float*)d_out;

    int B = in_sizes[0] / 1250;   // 16384
    int grid = (B + WARPS_PER_CTA - 1) / WARPS_PER_CTA;

    cudaFuncSetAttribute(gcn_kernel, cudaFuncAttributeMaxDynamicSharedMemorySize, SMEM_BYTES);
    gcn_kernel<<<grid, NTHREADS, SMEM_BYTES>>>(x, c1w, c1b, g1, be1, m1, v1,
                                               c2w, c2b, g2, be2, m2, v2,
                                               lw, lb, out, B);
}

// round 16
// speedup vs baseline: 1.7713x; 1.0601x over previous
#include <cuda_runtime.h>

#define WARPS_PER_CTA 12
#define NTHREADS (WARPS_PER_CTA * 32)

#define W1P_U 8800            // ull [275][32] packed (w,w), lane-major
#define W2P_U 5120            // ull [160][32] packed
#define LIN2_U 2496           // ull [6][13][32] packed (w_q, w_{q+6})
#define CONST_F (6*32 + 16)

#define SCRATCH_U 960         // ull slots per warp (7680 B)
#define SMEM_BYTES ((W1P_U + W2P_U + LIN2_U) * 8 + CONST_F * 4 + WARPS_PER_CTA * SCRATCH_U * 8)

typedef unsigned long long ull;

__device__ __forceinline__ ull pk2(float x, float y) {
    ull r; asm("mov.b64 %0, {%1,%2};" : "=l"(r) : "f"(x), "f"(y)); return r;
}
__device__ __forceinline__ void up2(ull v, float& x, float& y) {
    asm("mov.b64 {%0,%1}, %2;" : "=f"(x), "=f"(y) : "l"(v));
}
__device__ __forceinline__ ull swp(ull v) {
    float a, b; up2(v, a, b); return pk2(b, a);
}
__device__ __forceinline__ ull ffma2(ull a, ull b, ull c) {
    ull d; asm("fma.rn.f32x2 %0, %1, %2, %3;" : "=l"(d) : "l"(a), "l"(b), "l"(c)); return d;
}
__device__ __forceinline__ ull fadd2(ull a, ull b) {
    ull d; asm("add.rn.f32x2 %0, %1, %2;" : "=l"(d) : "l"(a), "l"(b)); return d;
}
// branch-free leaky relu on the fma/alu pipes (no predicate)
__device__ __forceinline__ float lrelu(float v) { return fmaxf(v, 0.2f * v); }

// integer warp reductions (single REDUX instruction; fp32 redux doesn't exist on sm_103)
__device__ __forceinline__ unsigned redux_max_u32(unsigned v) {
    unsigned r; asm("redux.sync.max.u32 %0, %1, 0xffffffff;" : "=r"(r) : "r"(v)); return r;
}
__device__ __forceinline__ unsigned redux_add_u32(unsigned v) {
    unsigned r; asm("redux.sync.add.u32 %0, %1, 0xffffffff;" : "=r"(r) : "r"(v)); return r;
}
__device__ __forceinline__ float warp_max_f(float f) {
    unsigned b = __float_as_uint(f);
    unsigned u = b ^ ((unsigned)((int)b >> 31) | 0x80000000u);     // monotone encode
    unsigned m = redux_max_u32(u);
    unsigned mb = m ^ ((unsigned)((int)(~m) >> 31) | 0x80000000u); // decode
    return __uint_as_float(mb);
}

// lane-softmax for ONE packed column: (ax, ay) raw leaky'd scores ->
// packed normalized attention weight for this lane.
// exp scaled by 2^25 folded into the exponent; integer-REDUX fixed-point sum
// (32 terms * 2^25 = 2^30 < 2^32; quantization rel-err ~5e-7).
__device__ __forceinline__ ull softmax_col(float ax, float ay) {
    const float L2E = 1.4426950408889634f;
    float mx = warp_max_f(ax), my = warp_max_f(ay);
    float tx = fmaf(-mx, L2E, 25.f), ty = fmaf(-my, L2E, 25.f);
    float exS = exp2f(fmaf(ax, L2E, tx));
    float eyS = exp2f(fmaf(ay, L2E, ty));
    unsigned sxu = redux_add_u32(__float2uint_rn(exS));
    unsigned syu = redux_add_u32(__float2uint_rn(eyS));
    return pk2(__fdividef(exS, (float)sxu), __fdividef(eyS, (float)syu));
}

__global__ void __launch_bounds__(NTHREADS, 1) gcn_kernel(
    const float* __restrict__ x,
    const float* __restrict__ c1w, const float* __restrict__ c1b,
    const float* __restrict__ g1,  const float* __restrict__ be1,
    const float* __restrict__ m1,  const float* __restrict__ v1,
    const float* __restrict__ c2w, const float* __restrict__ c2b,
    const float* __restrict__ g2,  const float* __restrict__ be2,
    const float* __restrict__ m2,  const float* __restrict__ v2,
    const float* __restrict__ lw,  const float* __restrict__ lb,
    float* __restrict__ out, int B)
{
    extern __shared__ ull smu[];
    ull*   w1P  = smu;                 // [k][32] packed (w,w)
    ull*   w2P  = w1P + W1P_U;
    ull*   lin2 = w2P + W2P_U;         // [q][j][32] packed (w_q, w_{q+6})
    float* sb1  = (float*)(lin2 + LIN2_U);
    float* sb2  = sb1 + 32;
    float* ss1  = sb2 + 32;
    float* sbb1 = ss1 + 32;
    float* ss2  = sbb1 + 32;
    float* sbb2 = ss2 + 32;
    float* slb  = sbb2 + 32;           // 16 floats (13 used)
    ull*   scratch = (ull*)(slb + 16);

    const int tid = threadIdx.x;

    // ---- cooperative weight staging (transposed, pre-packed) ----
    for (int i = tid; i < W1P_U; i += NTHREADS) {
        int k = i >> 5, o = i & 31;
        float w = c1w[o * 275 + k];
        w1P[i] = pk2(w, w);
    }
    for (int i = tid; i < W2P_U; i += NTHREADS) {
        int k = i >> 5, o = i & 31;
        float w = c2w[o * 160 + k];
        w2P[i] = pk2(w, w);
    }
    for (int i = tid; i < LIN2_U; i += NTHREADS) {
        int n = i & 31, tj = i >> 5;
        int j = tj % 13, q = tj / 13;          // q in 0..5
        lin2[i] = pk2(lw[j * 384 + n * 12 + q], lw[j * 384 + n * 12 + q + 6]);
    }
    if (tid < 32) {
        sb1[tid] = c1b[tid];
        sb2[tid] = c2b[tid];
        float inv1 = g1[tid] / sqrtf(v1[tid] + 1e-5f);
        ss1[tid] = inv1; sbb1[tid] = be1[tid] - m1[tid] * inv1;
        float inv2 = g2[tid] / sqrtf(v2[tid] + 1e-5f);
        ss2[tid] = inv2; sbb2[tid] = be2[tid] - m2[tid] * inv2;
    }
    if (tid < 13) slb[tid] = lb[tid];
    __syncthreads();

    const int warp = tid >> 5, lane = tid & 31;
    const int b = blockIdx.x * WARPS_PER_CTA + warp;
    if (b >= B) return;

    ull* scw = scratch + warp * SCRATCH_U;
    // phase-overlapped layouts (ull offsets within scw).
    // All lane-strided regions use ODD ull strides (gcd(stride,16)=1) so
    // 64-bit lane-strided stores are bank-conflict-free.
    ull* xpad2 = scw;            // [25][36]  (900)   conv1 input, packed (xa,na)
    ull* hsh2  = scw;            // [32][27]  (864)   layer-1 h rows (aliases xpad2)
    ull* ppad2 = scw;            // [32][17]  (544)   layer-2 padded input
    ull* cshN  = scw + 544;      // [32][13]  (416)   conv2 out rows (xa,na)

    // ---- stage input, circularly padded, packed (xa, na) ----
    const float* xb = x + (size_t)b * 1250;
    for (int i = lane; i < 900; i += 32) {
        int p = i % 36, ck = i / 36;     // ck = c*5 + h
        float vx = 0.f, vy = 0.f;
        if (p < 35) {
            int wsrc = (p + 20) % 25;    // padded p -> orig (p-5) mod 25
            vx = xb[ck * 50 + wsrc];
            vy = xb[ck * 50 + 25 + wsrc];
        }
        xpad2[i] = pk2(vx, vy);
    }
    __syncwarp();

    // ======== LAYER 1: conv1 (both branches packed) ========
    ull acc[25];
    {
        float bv = sb1[lane];
        ull bia = pk2(bv, bv);
#pragma unroll
        for (int w = 0; w < 25; w++) acc[w] = bia;
    }
#pragma unroll 1
    for (int ck = 0; ck < 25; ck++) {
        const ulonglong2* row2 = (const ulonglong2*)(xpad2 + ck * 36);
        ull xr[36];
#pragma unroll
        for (int q = 0; q < 18; q++) {
            ulonglong2 t = row2[q];
            xr[2*q] = t.x; xr[2*q+1] = t.y;
        }
        ull wr[11];
        const ull* wp = w1P + ck * 11 * 32 + lane;
#pragma unroll
        for (int kw = 0; kw < 11; kw++) wr[kw] = wp[kw * 32];
#pragma unroll
        for (int kw = 0; kw < 11; kw++)
#pragma unroll
            for (int w = 0; w < 25; w++)
                acc[w] = ffma2(wr[kw], xr[w + kw], acc[w]);
    }

    // h rows (with bias) to warp-local shared, packed (stride 27: conflict-free)
#pragma unroll
    for (int f = 0; f < 25; f++) hsh2[lane * 27 + f] = acc[f];
    __syncwarp();

    // ---- attention 1, STREAMED per column m: dot -> softmax -> AV ----
    ull o1[25];
#pragma unroll
    for (int f = 0; f < 25; f++) o1[f] = 0;
#pragma unroll 4
    for (int m = 0; m < 32; m++) {
        const ull* hm = hsh2 + m * 27;
        const ulonglong2* hm2 = (const ulonglong2*)hm;
        ull p0 = 0, p1 = 0;
#pragma unroll
        for (int q = 0; q < 12; q++) {
            ulonglong2 t = hm2[q];
            p0 = ffma2(acc[2*q],   t.x, p0);
            p1 = ffma2(acc[2*q+1], t.y, p1);
        }
        p0 = fadd2(p0, p1);
        p0 = ffma2(acc[24], hm[24], p0);
        float sx, sy; up2(p0, sx, sy);
        ull a = softmax_col(lrelu(sx), lrelu(sy));
#pragma unroll
        for (int q = 0; q < 12; q++) {
            ulonglong2 t = hm2[q];
            o1[2*q]   = ffma2(a, t.x, o1[2*q]);
            o1[2*q+1] = ffma2(a, t.y, o1[2*q+1]);
        }
        o1[24] = ffma2(a, hm[24], o1[24]);
    }

    // ---- BN1 -> pairwise maxpool (drop f=24) -> relu ----
    ull p2[12];
    {
        float s1 = ss1[lane], b1v = sbb1[lane];
        ull sc = pk2(s1, s1), bo = pk2(b1v, b1v);
#pragma unroll
        for (int j = 0; j < 12; j++) {
            ull y0 = ffma2(o1[2*j],   sc, bo);
            ull y1 = ffma2(o1[2*j+1], sc, bo);
            float a0, c0, a1, c1;
            up2(y0, a0, c0); up2(y1, a1, c1);
            p2[j] = pk2(fmaxf(fmaxf(a0, a1), 0.f), fmaxf(fmaxf(c0, c1), 0.f));
        }
    }
    __syncwarp();   // scratch reuse boundary (hsh2 dead)

    // ======== LAYER 2 ========
    {
        ull* pr = ppad2 + lane * 17;     // circular pad 2 on width 12 (stride 17: conflict-free)
#pragma unroll
        for (int j = 0; j < 12; j++) pr[2 + j] = p2[j];
        pr[0]  = p2[10]; pr[1]  = p2[11];
        pr[14] = p2[0];  pr[15] = p2[1];
    }
    __syncwarp();

    // conv2: 32 in-channels, 5 taps, width 12, packed branches
    ull a2[12];
    {
        float bv = sb2[lane];
        ull bia = pk2(bv, bv);
#pragma unroll
        for (int w = 0; w < 12; w++) a2[w] = bia;
    }
#pragma unroll 1
    for (int i = 0; i < 32; i++) {
        const ull* pr = ppad2 + i * 17;
        ull prr[16];
        {
            const ulonglong2* pr2 = (const ulonglong2*)pr;   // 16B-aligned (even base? i*17 odd!)
            // i*17 can be odd -> avoid vector loads; use scalar ull loads (broadcast)
#pragma unroll
            for (int q = 0; q < 16; q++) prr[q] = pr[q];
            (void)pr2;
        }
        ull wr[5];
        const ull* wp = w2P + i * 5 * 32 + lane;
#pragma unroll
        for (int kw = 0; kw < 5; kw++) wr[kw] = wp[kw * 32];
#pragma unroll
        for (int kw = 0; kw < 5; kw++)
#pragma unroll
            for (int w = 0; w < 12; w++)
                a2[w] = ffma2(wr[kw], prr[w + kw], a2[w]);
    }

    // store conv2 rows (xa,na) (stride 13: conflict-free); own swapped copy in regs
    ull c2s[12];
    {
        ull* cN = cshN + lane * 13;
#pragma unroll
        for (int w = 0; w < 12; w++) {
            cN[w] = a2[w];
            c2s[w] = swp(a2[w]);
        }
    }
    __syncwarp();

    // ---- attention 2 (cross branches), STREAMED ----
    // dot with own swapped rows gives a = (att_n2, att_x2).
    // AV trick: o2s[f] = sum_m swp(a_m) (x) h_m[f]  ==  (x2_val, n2_val)
    ull o2[12];
#pragma unroll
    for (int f = 0; f < 12; f++) o2[f] = 0;
#pragma unroll 4
    for (int m = 0; m < 32; m++) {
        const ull* hm = cshN + m * 13;
        ull hv[12];
        ull p0 = 0, p1 = 0;
#pragma unroll
        for (int q = 0; q < 6; q++) {
            hv[2*q]   = hm[2*q];
            hv[2*q+1] = hm[2*q+1];
            p0 = ffma2(c2s[2*q],   hv[2*q],   p0);
            p1 = ffma2(c2s[2*q+1], hv[2*q+1], p1);
        }
        p0 = fadd2(p0, p1);
        float sx, sy; up2(p0, sx, sy);
        ull a = swp(softmax_col(lrelu(sx), lrelu(sy)));   // (att_x2, att_n2)
#pragma unroll
        for (int f = 0; f < 12; f++)
            o2[f] = ffma2(a, hv[f], o2[f]);
    }

    // BN2 -> maxpool -> relu; o2 components are (x2_val, n2_val)
    float opx[6], opn[6];
    {
        float s2 = ss2[lane], b2v = sbb2[lane];
        ull sc = pk2(s2, s2), bo = pk2(b2v, b2v);
#pragma unroll
        for (int j = 0; j < 6; j++) {
            ull y0 = ffma2(o2[2*j],   sc, bo);
            ull y1 = ffma2(o2[2*j+1], sc, bo);
            float x0, n0, x1, n1;
            up2(y0, x0, n0); up2(y1, x1, n1);
            opx[j] = fmaxf(fmaxf(x0, x1), 0.f);
            opn[j] = fmaxf(fmaxf(n0, n1), 0.f);
        }
    }

    // ======== final linear (packed over branch pairs) ========
    ull part[13];
#pragma unroll
    for (int j = 0; j < 13; j++) part[j] = 0;
#pragma unroll
    for (int q = 0; q < 6; q++) {
        ull v = pk2(opx[q], opn[q]);
        const ull* wrow = lin2 + q * 13 * 32 + lane;
#pragma unroll
        for (int j = 0; j < 13; j++) part[j] = ffma2(v, wrow[j * 32], part[j]);
    }
    float ps[13];
#pragma unroll
    for (int j = 0; j < 13; j++) {
        float a, bq; up2(part[j], a, bq);
        ps[j] = a + bq;
    }
#pragma unroll
    for (int off = 16; off > 0; off >>= 1)
#pragma unroll
        for (int j = 0; j < 13; j++)
            ps[j] += __shfl_xor_sync(0xffffffffu, ps[j], off);

    if (lane == 0) {
#pragma unroll
        for (int j = 0; j < 13; j++)
            out[(size_t)b * 13 + j] = ps[j] + slb[j];
    }
}

extern "C" void kernel_launch(void* const* d_in, const int* in_sizes, int n_in,
                              void* d_out, int out_size) {
    const float* x   = (const float*)d_in[0];
    const float* c1w = (const float*)d_in[1];
    const float* c1b = (const float*)d_in[2];
    const float* g1  = (const float*)d_in[3];
    const float* be1 = (const float*)d_in[4];
    const float* m1  = (const float*)d_in[5];
    const float* v1  = (const float*)d_in[6];
    const float* c2w = (const float*)d_in[7];
    const float* c2b = (const float*)d_in[8];
    const float* g2  = (const float*)d_in[9];
    const float* be2 = (const float*)d_in[10];
    const float* m2  = (const float*)d_in[11];
    const float* v2  = (const float*)d_in[12];
    const float* lw  = (const float*)d_in[13];
    const float* lb  = (const float*)d_in[14];
    float* out = (float*)d_out;

    int B = in_sizes[0] / 1250;   // 16384
    int grid = (B + WARPS_PER_CTA - 1) / WARPS_PER_CTA;

    cudaFuncSetAttribute(gcn_kernel, cudaFuncAttributeMaxDynamicSharedMemorySize, SMEM_BYTES);
    gcn_kernel<<<grid, NTHREADS, SMEM_BYTES>>>(x, c1w, c1b, g1, be1, m1, v1,
                                               c2w, c2b, g2, be2, m2, v2,
                                               lw, lb, out, B);
}